// round 1
// baseline (speedup 1.0000x reference)
#include <cuda_runtime.h>
#include <cstdint>

// InstantNGP multiresolution hash-grid embedding.
// x:      [B, 3]  float32 in [-1, 1)
// tables: [16, 2^19, 2] float32
// out:    [B, 32] float32  (16 levels * 2 features, concatenated per level)
//
// One thread handles one (point, level) pair. tid = p*16 + level, so the
// final float2 store is fully coalesced (256B per warp).

#define NLVL 16
#define TSIZE (1u << 19)
#define TMASK (TSIZE - 1u)

// res_i = floor(16 * exp(i * ln(32)/15)) = floor(16 * 2^(i/3))
__constant__ int c_res[NLVL] = {16, 20, 25, 32, 40, 50, 64, 80,
                                101, 128, 161, 203, 256, 322, 406, 512};

__global__ __launch_bounds__(256) void hash_embed_kernel(
    const float* __restrict__ x,
    const float* __restrict__ tables,
    float* __restrict__ out,
    int B)
{
    int t = blockIdx.x * 256 + threadIdx.x;
    int p = t >> 4;          // point index
    if (p >= B) return;
    int lvl = t & 15;        // level index

    int res = c_res[lvl];
    float resf = (float)res;
    // Match reference rounding exactly: cell = 2/res (one f32 division),
    // pos = (x + 1) / cell (second f32 division). __fdiv_rn is IEEE
    // round-to-nearest regardless of fast-math compile flags.
    float cell = __fdiv_rn(2.0f, resf);

    float x0 = __ldg(x + 3 * p + 0);
    float x1 = __ldg(x + 3 * p + 1);
    float x2 = __ldg(x + 3 * p + 2);

    float p0 = __fdiv_rn(x0 + 1.0f, cell);
    float p1 = __fdiv_rn(x1 + 1.0f, cell);
    float p2 = __fdiv_rn(x2 + 1.0f, cell);

    int i0 = (int)floorf(p0); i0 = min(max(i0, 0), res - 1);
    int i1 = (int)floorf(p1); i1 = min(max(i1, 0), res - 1);
    int i2 = (int)floorf(p2); i2 = min(max(i2, 0), res - 1);

    // Fractional weights computed AFTER clipping (matches reference).
    float w0 = p0 - (float)i0;
    float w1 = p1 - (float)i1;
    float w2 = p2 - (float)i2;

    // Corner r: dx = (r>>2)&1, dy = (r>>1)&1, dz = r&1 (meshgrid 'ij' order).
    unsigned idx[8];
    if (res > 80) {
        // Spatial hash: h = (x*1) ^ (y*2654435761) ^ (z*805459861), uint32 wrap.
        unsigned a0 = (unsigned)i0;
        unsigned a1 = a0 + 1u;
        unsigned b0 = (unsigned)i1 * 2654435761u;
        unsigned b1 = b0 + 2654435761u;
        unsigned d0 = (unsigned)i2 * 805459861u;
        unsigned d1 = d0 + 805459861u;
        idx[0] = (a0 ^ b0 ^ d0) & TMASK;
        idx[1] = (a0 ^ b0 ^ d1) & TMASK;
        idx[2] = (a0 ^ b1 ^ d0) & TMASK;
        idx[3] = (a0 ^ b1 ^ d1) & TMASK;
        idx[4] = (a1 ^ b0 ^ d0) & TMASK;
        idx[5] = (a1 ^ b0 ^ d1) & TMASK;
        idx[6] = (a1 ^ b1 ^ d0) & TMASK;
        idx[7] = (a1 ^ b1 ^ d1) & TMASK;
    } else {
        // Linear unravel: x + res*y + res^2*z (int32, no clamp on the +1 side;
        // max index res + res^2 + res^3 < 2^19 for all linear levels).
        int r2 = res * res;
        int base = i0 + res * i1 + r2 * i2;
        idx[0] = (unsigned)(base);
        idx[1] = (unsigned)(base + r2);
        idx[2] = (unsigned)(base + res);
        idx[3] = (unsigned)(base + res + r2);
        idx[4] = (unsigned)(base + 1);
        idx[5] = (unsigned)(base + 1 + r2);
        idx[6] = (unsigned)(base + 1 + res);
        idx[7] = (unsigned)(base + 1 + res + r2);
    }

    const float2* __restrict__ tab =
        reinterpret_cast<const float2*>(tables) + (size_t)lvl * TSIZE;

    // Issue all 8 gathers back-to-back (MLP=8) before any dependent math.
    float2 v[8];
#pragma unroll
    for (int c = 0; c < 8; c++) v[c] = __ldg(tab + idx[c]);

    float u0 = 1.0f - w0, u1 = 1.0f - w1, u2 = 1.0f - w2;
    float wt[8];
    wt[0] = u0 * u1 * u2;
    wt[1] = u0 * u1 * w2;
    wt[2] = u0 * w1 * u2;
    wt[3] = u0 * w1 * w2;
    wt[4] = w0 * u1 * u2;
    wt[5] = w0 * u1 * w2;
    wt[6] = w0 * w1 * u2;
    wt[7] = w0 * w1 * w2;

    float s0 = 0.0f, s1 = 0.0f;
#pragma unroll
    for (int c = 0; c < 8; c++) {
        s0 += wt[c] * v[c].x;
        s1 += wt[c] * v[c].y;
    }

    reinterpret_cast<float2*>(out)[(size_t)p * 16 + lvl] = make_float2(s0, s1);
}

extern "C" void kernel_launch(void* const* d_in, const int* in_sizes, int n_in,
                              void* d_out, int out_size) {
    const float* x = (const float*)d_in[0];       // [B, 3]
    const float* tables = (const float*)d_in[1];  // [16, 2^19, 2]
    float* out = (float*)d_out;                   // [B, 32]
    int B = in_sizes[0] / 3;

    int total = B * NLVL;
    int blocks = (total + 255) / 256;
    hash_embed_kernel<<<blocks, 256>>>(x, tables, out, B);
}